// round 1
// baseline (speedup 1.0000x reference)
#include <cuda_runtime.h>
#include <math.h>

// LiquidNNSensorModel: 2-layer CfC RNN, B=256, T=1024, S=8, H=256.
// Strategy: batch-parallel persistent CTAs (G batches per CTA), h-state in SMEM,
// weights pre-transposed/interleaved (gate,backbone) pairs streamed from L2 as float4.
// No inter-CTA synchronization needed anywhere.

#define NB 256
#define NT 1024
#define NS 8
#define NH 256
#define G  4
#define NCTA (NB / G)   // 64 CTAs

// ---- scratch (static __device__: no allocation allowed) ----
// Interleaved transposed weight streams: entry (kb, o) holds k=4kb..4kb+3 as
// pairs (w_gate, w_backbone) for output neuron o. Two float4 per (kb,o).
__device__ float4 g_WA [64 * NH * 2];   // cell0 h-part: (gh_w0[o][k], bb_w0[o][8+k])
__device__ float4 g_WBX[64 * NH * 2];   // cell1 x-part: (gx_w1[o][k], bb_w1[o][k])
__device__ float4 g_WBH[64 * NH * 2];   // cell1 h-part: (gh_w1[o][k], bb_w1[o][256+k])
__device__ float2 g_WX0[NS * NH];       // cell0 x-part: (gx_w0[o][k], bb_w0[o][k])
__device__ float  g_bias[6 * NH];       // bg0, bf0, softplus(lt0), bg1, bf1, softplus(lt1)
__device__ float  g_dt[NB * NT];

// ---------------------------------------------------------------------------
__global__ void prep_dt_kernel(const float* __restrict__ ts) {
    int i = blockIdx.x * blockDim.x + threadIdx.x;
    if (i >= NB * NT) return;
    int t = i & (NT - 1);
    float dt = 1.0f;
    if (t > 0) dt = ts[i] - ts[i - 1];
    g_dt[i] = fmaxf(dt, 1e-6f);
}

__global__ void prep_w_kernel(
    const float* __restrict__ bb_w0, const float* __restrict__ bb_b0,
    const float* __restrict__ gx_w0, const float* __restrict__ gx_b0,
    const float* __restrict__ gh_w0, const float* __restrict__ gb0,
    const float* __restrict__ lt0,
    const float* __restrict__ bb_w1, const float* __restrict__ bb_b1,
    const float* __restrict__ gx_w1, const float* __restrict__ gx_b1,
    const float* __restrict__ gh_w1, const float* __restrict__ gb1,
    const float* __restrict__ lt1)
{
    const int kb = blockIdx.x;    // 0..63
    const int o  = threadIdx.x;   // 0..255
    const int k0 = kb * 4;
    {
        const float* gh = gh_w0 + o * NH;
        const float* bb = bb_w0 + o * (NS + NH) + NS;
        g_WA[(kb * NH + o) * 2 + 0] = make_float4(gh[k0],   bb[k0],   gh[k0+1], bb[k0+1]);
        g_WA[(kb * NH + o) * 2 + 1] = make_float4(gh[k0+2], bb[k0+2], gh[k0+3], bb[k0+3]);
    }
    {
        const float* gx = gx_w1 + o * NH;
        const float* bb = bb_w1 + o * (2 * NH);
        g_WBX[(kb * NH + o) * 2 + 0] = make_float4(gx[k0],   bb[k0],   gx[k0+1], bb[k0+1]);
        g_WBX[(kb * NH + o) * 2 + 1] = make_float4(gx[k0+2], bb[k0+2], gx[k0+3], bb[k0+3]);
    }
    {
        const float* gh = gh_w1 + o * NH;
        const float* bb = bb_w1 + o * (2 * NH) + NH;
        g_WBH[(kb * NH + o) * 2 + 0] = make_float4(gh[k0],   bb[k0],   gh[k0+1], bb[k0+1]);
        g_WBH[(kb * NH + o) * 2 + 1] = make_float4(gh[k0+2], bb[k0+2], gh[k0+3], bb[k0+3]);
    }
    if (kb == 0) {
        for (int k = 0; k < NS; k++)
            g_WX0[k * NH + o] = make_float2(gx_w0[o * NS + k], bb_w0[o * (NS + NH) + k]);
        g_bias[0 * NH + o] = gx_b0[o] + gb0[o];
        g_bias[1 * NH + o] = bb_b0[o];
        g_bias[2 * NH + o] = log1pf(expf(lt0[o]));   // softplus
        g_bias[3 * NH + o] = gx_b1[o] + gb1[o];
        g_bias[4 * NH + o] = bb_b1[o];
        g_bias[5 * NH + o] = log1pf(expf(lt1[o]));
    }
}

// ---------------------------------------------------------------------------
__global__ __launch_bounds__(256, 1) void liquid_main_kernel(
    const float* __restrict__ xs,       // [B,T,S]
    const float* __restrict__ ln_g, const float* __restrict__ ln_b,
    const float* __restrict__ lp_w, const float* __restrict__ lp_b,
    const float* __restrict__ r1_w, const float* __restrict__ r1_b,
    const float* __restrict__ r2_w, const float* __restrict__ r2_b,
    float* __restrict__ out)
{
    __shared__ float4 h0s[2][G][NH / 4];
    __shared__ float4 h1s[2][G][NH / 4];
    __shared__ float  xn_s[G][NS];
    __shared__ float  dt_s[G];
    __shared__ float  lat_s[G][32];

    const int tid    = threadIdx.x;      // = output neuron index o
    const int batch0 = blockIdx.x * G;

    // zero initial hidden states
    #pragma unroll
    for (int b = 0; b < G; b++) {
        ((float*)&h0s[0][b][0])[tid] = 0.f;
        ((float*)&h1s[0][b][0])[tid] = 0.f;
    }

    // per-thread constants (fixed o across all timesteps)
    const float rbg0 = g_bias[0 * NH + tid];
    const float rbf0 = g_bias[1 * NH + tid];
    const float rsp0 = g_bias[2 * NH + tid];
    const float rbg1 = g_bias[3 * NH + tid];
    const float rbf1 = g_bias[4 * NH + tid];
    const float rsp1 = g_bias[5 * NH + tid];
    float2 wx[NS];
    #pragma unroll
    for (int k = 0; k < NS; k++) wx[k] = g_WX0[k * NH + tid];

    float lng[NS], lnb[NS];
    if (tid < G) {
        #pragma unroll
        for (int k = 0; k < NS; k++) { lng[k] = ln_g[k]; lnb[k] = ln_b[k]; }
    }
    __syncthreads();

    int cur = 0;
    for (int t = 0; t < NT; t++) {
        const int nxt = cur ^ 1;

        // ---- input layernorm (one thread per batch element) ----
        if (tid < G) {
            const int batch = batch0 + tid;
            const float4* xp = (const float4*)(xs + ((size_t)batch * NT + t) * NS);
            const float4 a = xp[0], c = xp[1];
            float x[NS] = {a.x, a.y, a.z, a.w, c.x, c.y, c.z, c.w};
            float mu = 0.f;
            #pragma unroll
            for (int k = 0; k < NS; k++) mu += x[k];
            mu *= 0.125f;
            float var = 0.f;
            #pragma unroll
            for (int k = 0; k < NS; k++) { float d = x[k] - mu; var += d * d; }
            var *= 0.125f;
            const float inv = rsqrtf(var + 1e-5f);
            #pragma unroll
            for (int k = 0; k < NS; k++)
                xn_s[tid][k] = (x[k] - mu) * inv * lng[k] + lnb[k];
            dt_s[tid] = g_dt[batch * NT + t];
        }
        __syncthreads();

        // =================== stage A: CfC cell 0 ===================
        float ag[G], af[G];
        #pragma unroll
        for (int b = 0; b < G; b++) { ag[b] = rbg0; af[b] = rbf0; }
        // x-part (K=8)
        #pragma unroll
        for (int k = 0; k < NS; k++) {
            const float2 w = wx[k];
            #pragma unroll
            for (int b = 0; b < G; b++) {
                const float xk = xn_s[b][k];
                ag[b] = fmaf(w.x, xk, ag[b]);
                af[b] = fmaf(w.y, xk, af[b]);
            }
        }
        // h-part (K=256): stream interleaved weights; h reads are SMEM broadcasts
        {
            const float4* Wp = g_WA + tid * 2;
            #pragma unroll 4
            for (int kb = 0; kb < 64; kb++) {
                const float4 w0 = Wp[kb * (NH * 2) + 0];
                const float4 w1 = Wp[kb * (NH * 2) + 1];
                #pragma unroll
                for (int b = 0; b < G; b++) {
                    const float4 h = h0s[cur][b][kb];
                    ag[b] = fmaf(w0.x, h.x, ag[b]); af[b] = fmaf(w0.y, h.x, af[b]);
                    ag[b] = fmaf(w0.z, h.y, ag[b]); af[b] = fmaf(w0.w, h.y, af[b]);
                    ag[b] = fmaf(w1.x, h.z, ag[b]); af[b] = fmaf(w1.y, h.z, af[b]);
                    ag[b] = fmaf(w1.z, h.w, ag[b]); af[b] = fmaf(w1.w, h.w, af[b]);
                }
            }
        }
        #pragma unroll
        for (int b = 0; b < G; b++) {
            const float g   = 1.f / (1.f + __expf(-ag[b]));
            const float f   = tanhf(af[b]);
            const float tau = rsp0 + fabsf(g);
            const float dcy = __expf(-dt_s[b] * tau);
            const float hp  = ((const float*)&h0s[cur][b][0])[tid];
            ((float*)&h0s[nxt][b][0])[tid] = dcy * hp + (1.f - dcy) * f;
        }
        __syncthreads();

        // =================== stage B: CfC cell 1 ===================
        #pragma unroll
        for (int b = 0; b < G; b++) { ag[b] = rbg1; af[b] = rbf1; }
        {
            const float4* Wp = g_WBX + tid * 2;   // input = h0_new
            #pragma unroll 4
            for (int kb = 0; kb < 64; kb++) {
                const float4 w0 = Wp[kb * (NH * 2) + 0];
                const float4 w1 = Wp[kb * (NH * 2) + 1];
                #pragma unroll
                for (int b = 0; b < G; b++) {
                    const float4 h = h0s[nxt][b][kb];
                    ag[b] = fmaf(w0.x, h.x, ag[b]); af[b] = fmaf(w0.y, h.x, af[b]);
                    ag[b] = fmaf(w0.z, h.y, ag[b]); af[b] = fmaf(w0.w, h.y, af[b]);
                    ag[b] = fmaf(w1.x, h.z, ag[b]); af[b] = fmaf(w1.y, h.z, af[b]);
                    ag[b] = fmaf(w1.z, h.w, ag[b]); af[b] = fmaf(w1.w, h.w, af[b]);
                }
            }
        }
        {
            const float4* Wq = g_WBH + tid * 2;   // input = h1_prev
            #pragma unroll 4
            for (int kb = 0; kb < 64; kb++) {
                const float4 w0 = Wq[kb * (NH * 2) + 0];
                const float4 w1 = Wq[kb * (NH * 2) + 1];
                #pragma unroll
                for (int b = 0; b < G; b++) {
                    const float4 h = h1s[cur][b][kb];
                    ag[b] = fmaf(w0.x, h.x, ag[b]); af[b] = fmaf(w0.y, h.x, af[b]);
                    ag[b] = fmaf(w0.z, h.y, ag[b]); af[b] = fmaf(w0.w, h.y, af[b]);
                    ag[b] = fmaf(w1.x, h.z, ag[b]); af[b] = fmaf(w1.y, h.z, af[b]);
                    ag[b] = fmaf(w1.z, h.w, ag[b]); af[b] = fmaf(w1.w, h.w, af[b]);
                }
            }
        }
        #pragma unroll
        for (int b = 0; b < G; b++) {
            const float g   = 1.f / (1.f + __expf(-ag[b]));
            const float f   = tanhf(af[b]);
            const float tau = rsp1 + fabsf(g);
            const float dcy = __expf(-dt_s[b] * tau);
            const float hp  = ((const float*)&h1s[cur][b][0])[tid];
            ((float*)&h1s[nxt][b][0])[tid] = dcy * hp + (1.f - dcy) * f;
        }
        __syncthreads();
        cur = nxt;
    }

    // =================== head: latent + risk ===================
    if (tid < G * 32) {
        const int b = tid >> 5, l = tid & 31;
        const float* hv   = (const float*)&h1s[cur][b][0];
        const float* wrow = lp_w + l * NH;
        float acc = lp_b[l];
        for (int k = 0; k < NH; k++) acc = fmaf(hv[k], __ldg(wrow + k), acc);
        const float lat = tanhf(acc);
        lat_s[b][l] = lat;
        out[(size_t)(batch0 + b) * 32 + l] = lat;
    }
    __syncthreads();
    if (tid < G * 32) {
        const int b = tid >> 5, j = tid & 31;
        const float* wrow = r1_w + j * 32;
        float acc = r1_b[j];
        #pragma unroll
        for (int k = 0; k < 32; k++) acc = fmaf(lat_s[b][k], __ldg(wrow + k), acc);
        // exact GELU (erf form, matches approximate=False)
        const float hid = 0.5f * acc * (1.f + erff(acc * 0.70710678118654752f));
        float v = hid * __ldg(r2_w + j);
        #pragma unroll
        for (int off = 16; off; off >>= 1) v += __shfl_xor_sync(0xffffffffu, v, off);
        if (j == 0) {
            const float risk = 1.f / (1.f + __expf(-(v + r2_b[0])));
            out[NB * 32 + batch0 + b] = risk;
        }
    }
}

// ---------------------------------------------------------------------------
extern "C" void kernel_launch(void* const* d_in, const int* in_sizes, int n_in,
                              void* d_out, int out_size) {
    const float* xs    = (const float*)d_in[0];
    const float* ts    = (const float*)d_in[1];
    const float* ln_g  = (const float*)d_in[2];
    const float* ln_b  = (const float*)d_in[3];
    const float* bb_w0 = (const float*)d_in[4];
    const float* bb_b0 = (const float*)d_in[5];
    const float* gx_w0 = (const float*)d_in[6];
    const float* gx_b0 = (const float*)d_in[7];
    const float* gh_w0 = (const float*)d_in[8];
    const float* gb0   = (const float*)d_in[9];
    const float* lt0   = (const float*)d_in[10];
    const float* bb_w1 = (const float*)d_in[11];
    const float* bb_b1 = (const float*)d_in[12];
    const float* gx_w1 = (const float*)d_in[13];
    const float* gx_b1 = (const float*)d_in[14];
    const float* gh_w1 = (const float*)d_in[15];
    const float* gb1   = (const float*)d_in[16];
    const float* lt1   = (const float*)d_in[17];
    const float* lp_w  = (const float*)d_in[18];
    const float* lp_b  = (const float*)d_in[19];
    const float* r1_w  = (const float*)d_in[20];
    const float* r1_b  = (const float*)d_in[21];
    const float* r2_w  = (const float*)d_in[22];
    const float* r2_b  = (const float*)d_in[23];
    float* out = (float*)d_out;

    prep_dt_kernel<<<(NB * NT) / 256, 256>>>(ts);
    prep_w_kernel<<<64, 256>>>(bb_w0, bb_b0, gx_w0, gx_b0, gh_w0, gb0, lt0,
                               bb_w1, bb_b1, gx_w1, gx_b1, gh_w1, gb1, lt1);
    liquid_main_kernel<<<NCTA, 256>>>(xs, ln_g, ln_b, lp_w, lp_b,
                                      r1_w, r1_b, r2_w, r2_b, out);
}